// round 6
// baseline (speedup 1.0000x reference)
#include <cuda_runtime.h>
#include <math.h>

// Shapes (fixed by the problem)
#define T 2048
#define B 32
#define H 1024
#define KSPLIT 8           // k-tiles of 128 for the v GEMM
#define NCHUNK 16          // score-chunks per b (128 t each)

// Scratch (allocation-free rule: __device__ globals)
__device__ float g_vpart[KSPLIT][B][H];   // 1 MB split-k partials
__device__ float g_v[B][H];               // 128 KB  v = hid @ W
__device__ float g_scores[B][T];          // 256 KB  pre-softmax scores
__device__ float g_pm[B][NCHUNK];         // per-chunk local max
__device__ float g_ps[B][NCHUNK];         // per-chunk local sum of exp
__device__ int   g_cntv[8];               // arrival counters (v groups)
__device__ int   g_cnts[B];               // arrival counters (score chunks)

// ---------------------------------------------------------------------------
// K1: v = hid @ W, single kernel.
// Phase 1 (all 64 blocks): v_part[ks][b][h] over ktile=128.
//   grid (hchunk=2, bgroup=4, ksplit=8) x 128 threads; thread: 4h x 8b x 128k.
// Phase 2 (last block of each (hchunk,bgroup) group of 8): sums the 8
//   partials for its 8b x 512h region and writes g_v. Counter reset in-kernel.
// Deterministic: fixed summation order, int atomics only used as a ticket.
// ---------------------------------------------------------------------------
__global__ void __launch_bounds__(128) k_v(const float* __restrict__ hid,
                                           const float* __restrict__ W) {
    __shared__ float hid_s[8][128];
    __shared__ int s_old;
    const int tid   = threadIdx.x;          // 0..127
    const int h0    = blockIdx.x * 512 + tid * 4;
    const int bbase = blockIdx.y * 8;
    const int kbase = blockIdx.z * 128;
    const int group = blockIdx.x * 4 + blockIdx.y;   // 0..7

    for (int i = tid; i < 8 * 128; i += 128) {
        int bb = i >> 7, kk = i & 127;
        hid_s[bb][kk] = hid[(bbase + bb) * H + kbase + kk];
    }
    __syncthreads();

    float4 acc[8];
#pragma unroll
    for (int bb = 0; bb < 8; bb++) acc[bb] = make_float4(0.f, 0.f, 0.f, 0.f);

#pragma unroll 4
    for (int kk = 0; kk < 128; kk++) {
        float4 w = *reinterpret_cast<const float4*>(&W[(size_t)(kbase + kk) * H + h0]);
#pragma unroll
        for (int bb = 0; bb < 8; bb++) {
            float hv = hid_s[bb][kk];
            acc[bb].x += hv * w.x;
            acc[bb].y += hv * w.y;
            acc[bb].z += hv * w.z;
            acc[bb].w += hv * w.w;
        }
    }

#pragma unroll
    for (int bb = 0; bb < 8; bb++) {
        *reinterpret_cast<float4*>(&g_vpart[blockIdx.z][bbase + bb][h0]) = acc[bb];
    }

    // release: partial writes -> visible before ticket
    __syncthreads();
    if (tid == 0) {
        __threadfence();
        s_old = atomicAdd(&g_cntv[group], 1);
    }
    __syncthreads();

    if (s_old == KSPLIT - 1) {                       // last arriver reduces
        __threadfence();                             // acquire
#pragma unroll
        for (int bb = 0; bb < 8; bb++) {
            float4 s = make_float4(0.f, 0.f, 0.f, 0.f);
#pragma unroll
            for (int p = 0; p < KSPLIT; p++) {
                float4 v = *reinterpret_cast<const float4*>(&g_vpart[p][bbase + bb][h0]);
                s.x += v.x; s.y += v.y; s.z += v.z; s.w += v.w;
            }
            *reinterpret_cast<float4*>(&g_v[bbase + bb][h0]) = s;
        }
        if (tid == 0) g_cntv[group] = 0;             // replay-safe reset
    }
}

// ---------------------------------------------------------------------------
// K2: scores + softmax, fused.
// Block = one b x 128 t (8 warps x 16 t). grid 512 x 256.
// Stream body identical to the proven R2 kernel: v[b] in registers, all 128
// enc loads per warp independent (__ldcs, max MLP), one pipelined butterfly
// strictly after all loads. Epilogue: per-warp (m, sum-exp) partial -> block
// partial -> global chunk partial; the 16th block per b merges 16 partials
// and writes the final softmax outputs for its b (8 KB from L2).
// ---------------------------------------------------------------------------
__global__ void __launch_bounds__(256) k_scores(const float* __restrict__ enc,
                                                float* __restrict__ out) {
    __shared__ float sm_m[8], sm_s[8];
    __shared__ float sm_M, sm_inv;
    __shared__ int s_old;
    const int warp  = threadIdx.x >> 5;
    const int lane  = threadIdx.x & 31;
    const int b     = blockIdx.x >> 4;       // 0..31
    const int chunk = blockIdx.x & 15;       // 0..15
    const int tbase = chunk * 128 + warp * 16;

    // v[b] into registers: 8 float4 per lane (lane covers h = i*128 + lane*4)
    float4 vreg[8];
#pragma unroll
    for (int i = 0; i < 8; i++) {
        vreg[i] = *reinterpret_cast<const float4*>(&g_v[b][i * 128 + lane * 4]);
    }

    float acc[16];
#pragma unroll
    for (int tt = 0; tt < 16; tt++) {
        const int t = tbase + tt;
        const float4* e = reinterpret_cast<const float4*>(
            enc + ((size_t)t * B + b) * H) + lane;   // lane*4 floats in
        float4 a = make_float4(0.f, 0.f, 0.f, 0.f);
#pragma unroll
        for (int i = 0; i < 8; i++) {
            float4 ev = __ldcs(&e[i * 32]);          // h = i*128 + lane*4
            a.x += ev.x * vreg[i].x;
            a.y += ev.y * vreg[i].y;
            a.z += ev.z * vreg[i].z;
            a.w += ev.w * vreg[i].w;
        }
        acc[tt] = (a.x + a.y) + (a.z + a.w);
    }

    // Pipelined multi-value butterfly: 16 independent 5-stage chains.
#pragma unroll
    for (int off = 16; off > 0; off >>= 1) {
#pragma unroll
        for (int i = 0; i < 16; i++)
            acc[i] += __shfl_xor_sync(0xFFFFFFFFu, acc[i], off);
    }

    // per-warp softmax partial (computed after all loads retired)
    float mg = acc[0];
#pragma unroll
    for (int i = 1; i < 16; i++) mg = fmaxf(mg, acc[i]);
    float sg = 0.f;
#pragma unroll
    for (int i = 0; i < 16; i++) sg += __expf(acc[i] - mg);

    if (lane == 0) {
#pragma unroll
        for (int i = 0; i < 16; i++) g_scores[b][tbase + i] = acc[i];
        sm_m[warp] = mg;
        sm_s[warp] = sg;
    }
    __syncthreads();

    // merge 8 warp partials -> chunk partial; publish; take ticket
    if (threadIdx.x == 0) {
        float M = sm_m[0], S = sm_s[0];
#pragma unroll
        for (int i = 1; i < 8; i++) {
            float mi = sm_m[i];
            float nm = fmaxf(M, mi);
            S = S * __expf(M - nm) + sm_s[i] * __expf(mi - nm);
            M = nm;
        }
        g_pm[b][chunk] = M;
        g_ps[b][chunk] = S;
        __threadfence();                              // release
        s_old = atomicAdd(&g_cnts[b], 1);
    }
    __syncthreads();

    if (s_old == NCHUNK - 1) {                        // last chunk of this b
        __threadfence();                              // acquire
        if (threadIdx.x < 32) {
            float m = (lane < NCHUNK) ? g_pm[b][lane] : -INFINITY;
            float s = (lane < NCHUNK) ? g_ps[b][lane] : 0.f;
#pragma unroll
            for (int off = 8; off > 0; off >>= 1) {
                float mo = __shfl_xor_sync(0xFFFFFFFFu, m, off);
                float so = __shfl_xor_sync(0xFFFFFFFFu, s, off);
                float nm = fmaxf(m, mo);
                s = s * __expf(m - nm) + so * __expf(mo - nm);
                m = nm;
            }
            if (lane == 0) { sm_M = m; sm_inv = 1.f / s; }
        }
        __syncthreads();
        const float M = sm_M, inv = sm_inv;
#pragma unroll
        for (int j = 0; j < 2; j++) {
            const int t0 = j * 1024 + threadIdx.x * 4;
            float4 sc = *reinterpret_cast<const float4*>(&g_scores[b][t0]);
            float4 o;
            o.x = __expf(sc.x - M) * inv;
            o.y = __expf(sc.y - M) * inv;
            o.z = __expf(sc.z - M) * inv;
            o.w = __expf(sc.w - M) * inv;
            *reinterpret_cast<float4*>(&out[(size_t)b * T + t0]) = o;
        }
        if (threadIdx.x == 0) g_cnts[b] = 0;          // replay-safe reset
    }
}

// ---------------------------------------------------------------------------
// Inputs (metadata order): hidden [1,B,H], encoderOutput [T,B,H], W [H,H], b [H]
// Output: [B,1,T] float32.  Bias is constant in t -> cancels in softmax.
// ---------------------------------------------------------------------------
extern "C" void kernel_launch(void* const* d_in, const int* in_sizes, int n_in,
                              void* d_out, int out_size) {
    const float* hid = (const float*)d_in[0];
    const float* enc = (const float*)d_in[1];
    const float* W   = (const float*)d_in[2];
    (void)in_sizes; (void)n_in; (void)out_size;
    float* out = (float*)d_out;

    k_v<<<dim3(2, 4, KSPLIT), 128>>>(hid, W);
    k_scores<<<512, 256>>>(enc, out);
}

// round 7
// speedup vs baseline: 1.0210x; 1.0210x over previous
#include <cuda_runtime.h>
#include <math.h>

// Shapes (fixed by the problem)
#define T 2048
#define B 32
#define H 1024
#define KSPLIT 32          // k-tiles of 32 for the v GEMV
#define NCHUNK 16          // score-chunks per b (128 t each)

// Scratch (allocation-free rule: __device__ globals)
__device__ float g_vpart[KSPLIT][B][H];   // 4 MB split-k partials (L2-resident)
__device__ float g_v[B][H];               // 128 KB  v = hid @ W
__device__ float g_scores[B][T];          // 256 KB  pre-softmax scores
__device__ float g_pm[B][NCHUNK];         // per-chunk local max
__device__ float g_ps[B][NCHUNK];         // per-chunk local sum of exp
__device__ int   g_cntv[8];               // arrival counters (v groups)
__device__ int   g_cnts[B];               // arrival counters (score chunks)

// ---------------------------------------------------------------------------
// K1: v = hid @ W, single kernel, HIGH parallelism.
// Phase 1: grid (hchunk=2, bgroup=4, ksplit=32) = 256 blocks x 128 threads;
//   thread: 4 h (float4) x 8 b x 32 k.  (R2's proven ~2.5us shape.)
// Phase 2: last arriver of each (hchunk,bgroup) group of 32 sums the 32
//   partials for its 8b x 512h region (4 MB total, L2-resident, independent
//   loads) and writes g_v. Counters reset in-kernel -> graph-replay safe.
// Deterministic: fixed summation order; atomics only as arrival tickets.
// ---------------------------------------------------------------------------
__global__ void __launch_bounds__(128) k_v(const float* __restrict__ hid,
                                           const float* __restrict__ W) {
    __shared__ float hid_s[8][32];
    __shared__ int s_old;
    const int tid   = threadIdx.x;          // 0..127
    const int h0    = blockIdx.x * 512 + tid * 4;
    const int bbase = blockIdx.y * 8;
    const int kbase = blockIdx.z * 32;
    const int group = blockIdx.x * 4 + blockIdx.y;   // 0..7

    for (int i = tid; i < 8 * 32; i += 128) {
        int bb = i >> 5, kk = i & 31;
        hid_s[bb][kk] = hid[(bbase + bb) * H + kbase + kk];
    }
    __syncthreads();

    float4 acc[8];
#pragma unroll
    for (int bb = 0; bb < 8; bb++) acc[bb] = make_float4(0.f, 0.f, 0.f, 0.f);

#pragma unroll 4
    for (int kk = 0; kk < 32; kk++) {
        float4 w = *reinterpret_cast<const float4*>(&W[(size_t)(kbase + kk) * H + h0]);
#pragma unroll
        for (int bb = 0; bb < 8; bb++) {
            float hv = hid_s[bb][kk];
            acc[bb].x += hv * w.x;
            acc[bb].y += hv * w.y;
            acc[bb].z += hv * w.z;
            acc[bb].w += hv * w.w;
        }
    }

#pragma unroll
    for (int bb = 0; bb < 8; bb++) {
        *reinterpret_cast<float4*>(&g_vpart[blockIdx.z][bbase + bb][h0]) = acc[bb];
    }

    // release: partial writes -> visible before ticket
    __syncthreads();
    if (tid == 0) {
        __threadfence();
        s_old = atomicAdd(&g_cntv[group], 1);
    }
    __syncthreads();

    if (s_old == KSPLIT - 1) {                       // last arriver reduces
        __threadfence();                             // acquire
#pragma unroll
        for (int bb = 0; bb < 8; bb++) {
            float4 s = make_float4(0.f, 0.f, 0.f, 0.f);
#pragma unroll
            for (int p = 0; p < KSPLIT; p++) {
                float4 v = *reinterpret_cast<const float4*>(&g_vpart[p][bbase + bb][h0]);
                s.x += v.x; s.y += v.y; s.z += v.z; s.w += v.w;
            }
            *reinterpret_cast<float4*>(&g_v[bbase + bb][h0]) = s;
        }
        if (tid == 0) g_cntv[group] = 0;             // replay-safe reset
    }
}

// ---------------------------------------------------------------------------
// K2: scores + softmax, fused (unchanged from R6 -- measured 49.7us).
// Block = one b x 128 t (8 warps x 16 t). grid 512 x 256.
// Stream body: v[b] in registers, all 128 enc loads per warp independent
// (__ldcs, max MLP), one pipelined butterfly strictly after all loads.
// Epilogue: warp (m,s) -> block partial -> global; 16th block per b merges
// and writes the final softmax outputs for its b (8 KB via L2).
// ---------------------------------------------------------------------------
__global__ void __launch_bounds__(256) k_scores(const float* __restrict__ enc,
                                                float* __restrict__ out) {
    __shared__ float sm_m[8], sm_s[8];
    __shared__ float sm_M, sm_inv;
    __shared__ int s_old;
    const int warp  = threadIdx.x >> 5;
    const int lane  = threadIdx.x & 31;
    const int b     = blockIdx.x >> 4;       // 0..31
    const int chunk = blockIdx.x & 15;       // 0..15
    const int tbase = chunk * 128 + warp * 16;

    // v[b] into registers: 8 float4 per lane (lane covers h = i*128 + lane*4)
    float4 vreg[8];
#pragma unroll
    for (int i = 0; i < 8; i++) {
        vreg[i] = *reinterpret_cast<const float4*>(&g_v[b][i * 128 + lane * 4]);
    }

    float acc[16];
#pragma unroll
    for (int tt = 0; tt < 16; tt++) {
        const int t = tbase + tt;
        const float4* e = reinterpret_cast<const float4*>(
            enc + ((size_t)t * B + b) * H) + lane;   // lane*4 floats in
        float4 a = make_float4(0.f, 0.f, 0.f, 0.f);
#pragma unroll
        for (int i = 0; i < 8; i++) {
            float4 ev = __ldcs(&e[i * 32]);          // h = i*128 + lane*4
            a.x += ev.x * vreg[i].x;
            a.y += ev.y * vreg[i].y;
            a.z += ev.z * vreg[i].z;
            a.w += ev.w * vreg[i].w;
        }
        acc[tt] = (a.x + a.y) + (a.z + a.w);
    }

    // Pipelined multi-value butterfly: 16 independent 5-stage chains.
#pragma unroll
    for (int off = 16; off > 0; off >>= 1) {
#pragma unroll
        for (int i = 0; i < 16; i++)
            acc[i] += __shfl_xor_sync(0xFFFFFFFFu, acc[i], off);
    }

    // per-warp softmax partial (computed after all loads retired)
    float mg = acc[0];
#pragma unroll
    for (int i = 1; i < 16; i++) mg = fmaxf(mg, acc[i]);
    float sg = 0.f;
#pragma unroll
    for (int i = 0; i < 16; i++) sg += __expf(acc[i] - mg);

    if (lane == 0) {
#pragma unroll
        for (int i = 0; i < 16; i++) g_scores[b][tbase + i] = acc[i];
        sm_m[warp] = mg;
        sm_s[warp] = sg;
    }
    __syncthreads();

    // merge 8 warp partials -> chunk partial; publish; take ticket
    if (threadIdx.x == 0) {
        float M = sm_m[0], S = sm_s[0];
#pragma unroll
        for (int i = 1; i < 8; i++) {
            float mi = sm_m[i];
            float nm = fmaxf(M, mi);
            S = S * __expf(M - nm) + sm_s[i] * __expf(mi - nm);
            M = nm;
        }
        g_pm[b][chunk] = M;
        g_ps[b][chunk] = S;
        __threadfence();                              // release
        s_old = atomicAdd(&g_cnts[b], 1);
    }
    __syncthreads();

    if (s_old == NCHUNK - 1) {                        // last chunk of this b
        __threadfence();                              // acquire
        if (threadIdx.x < 32) {
            float m = (lane < NCHUNK) ? g_pm[b][lane] : -INFINITY;
            float s = (lane < NCHUNK) ? g_ps[b][lane] : 0.f;
#pragma unroll
            for (int off = 8; off > 0; off >>= 1) {
                float mo = __shfl_xor_sync(0xFFFFFFFFu, m, off);
                float so = __shfl_xor_sync(0xFFFFFFFFu, s, off);
                float nm = fmaxf(m, mo);
                s = s * __expf(m - nm) + so * __expf(mo - nm);
                m = nm;
            }
            if (lane == 0) { sm_M = m; sm_inv = 1.f / s; }
        }
        __syncthreads();
        const float M = sm_M, inv = sm_inv;
#pragma unroll
        for (int j = 0; j < 2; j++) {
            const int t0 = j * 1024 + threadIdx.x * 4;
            float4 sc = *reinterpret_cast<const float4*>(&g_scores[b][t0]);
            float4 o;
            o.x = __expf(sc.x - M) * inv;
            o.y = __expf(sc.y - M) * inv;
            o.z = __expf(sc.z - M) * inv;
            o.w = __expf(sc.w - M) * inv;
            *reinterpret_cast<float4*>(&out[(size_t)b * T + t0]) = o;
        }
        if (threadIdx.x == 0) g_cnts[b] = 0;          // replay-safe reset
    }
}

// ---------------------------------------------------------------------------
// Inputs (metadata order): hidden [1,B,H], encoderOutput [T,B,H], W [H,H], b [H]
// Output: [B,1,T] float32.  Bias is constant in t -> cancels in softmax.
// ---------------------------------------------------------------------------
extern "C" void kernel_launch(void* const* d_in, const int* in_sizes, int n_in,
                              void* d_out, int out_size) {
    const float* hid = (const float*)d_in[0];
    const float* enc = (const float*)d_in[1];
    const float* W   = (const float*)d_in[2];
    (void)in_sizes; (void)n_in; (void)out_size;
    float* out = (float*)d_out;

    k_v<<<dim3(2, 4, KSPLIT), 128>>>(hid, W);
    k_scores<<<512, 256>>>(enc, out);
}

// round 8
// speedup vs baseline: 1.1798x; 1.1555x over previous
#include <cuda_runtime.h>
#include <math.h>

// Shapes (fixed by the problem)
#define T 2048
#define B 32
#define H 1024
#define KSPLIT 32          // k-tiles of 32 for the v GEMV
#define NCHUNK 16          // score-chunks per b (128 t each)

// Scratch (allocation-free rule: __device__ globals)
__device__ float g_vpart[KSPLIT][B][H];   // 4 MB split-k partials (L2-resident)
__device__ float g_v[B][H];               // 128 KB  v = hid @ W
__device__ float g_scores[B][T];          // 256 KB  pre-softmax scores
__device__ float g_pm[B][NCHUNK];         // per-chunk local max
__device__ float g_ps[B][NCHUNK];         // per-chunk local sum of exp
__device__ int   g_cnts[B];               // arrival counters (score chunks)

// ---------------------------------------------------------------------------
// K1: v_part[ks][b][h] = sum over k in [ks*32, ks*32+32) of hid[b,k]*W[k,h]
// grid: (hchunk=2, bgroup=4, ksplit=32) = 256 blocks x 128 threads (R2 shape).
// Plain split-k: no atomics, no fences. Deterministic.
// ---------------------------------------------------------------------------
__global__ void __launch_bounds__(128) k_vpart(const float* __restrict__ hid,
                                               const float* __restrict__ W) {
    __shared__ float hid_s[8][32];
    const int tid   = threadIdx.x;          // 0..127
    const int h0    = blockIdx.x * 512 + tid * 4;
    const int bbase = blockIdx.y * 8;
    const int kbase = blockIdx.z * 32;

    for (int i = tid; i < 8 * 32; i += 128) {
        int bb = i >> 5, kk = i & 31;
        hid_s[bb][kk] = hid[(bbase + bb) * H + kbase + kk];
    }
    __syncthreads();

    float4 acc[8];
#pragma unroll
    for (int bb = 0; bb < 8; bb++) acc[bb] = make_float4(0.f, 0.f, 0.f, 0.f);

#pragma unroll 4
    for (int kk = 0; kk < 32; kk++) {
        float4 w = *reinterpret_cast<const float4*>(&W[(size_t)(kbase + kk) * H + h0]);
#pragma unroll
        for (int bb = 0; bb < 8; bb++) {
            float hv = hid_s[bb][kk];
            acc[bb].x += hv * w.x;
            acc[bb].y += hv * w.y;
            acc[bb].z += hv * w.z;
            acc[bb].w += hv * w.w;
        }
    }

#pragma unroll
    for (int bb = 0; bb < 8; bb++) {
        *reinterpret_cast<float4*>(&g_vpart[blockIdx.z][bbase + bb][h0]) = acc[bb];
    }
}

// ---------------------------------------------------------------------------
// K2: v[b][h] = sum over ksplit of v_part   (32768 elems; vpart sits in L2)
// ---------------------------------------------------------------------------
__global__ void __launch_bounds__(256) k_vreduce() {
    int idx = blockIdx.x * blockDim.x + threadIdx.x;
    const float* vp = &g_vpart[0][0][0];
    float* v = &g_v[0][0];
    if (idx < B * H) {
        float s = 0.f;
#pragma unroll
        for (int p = 0; p < KSPLIT; p++) s += vp[p * (B * H) + idx];
        v[idx] = s;
    }
}

// ---------------------------------------------------------------------------
// K3: scores + softmax, fused (byte-identical to R7 -- measured 50.1us).
// Block = one b x 128 t (8 warps x 16 t). grid 512 x 256.
// Stream body: v[b] in registers, all 128 enc loads per warp independent
// (__ldcs, max MLP), one pipelined butterfly strictly after all loads.
// Epilogue: warp (m,s) -> block partial -> global; 16th block per b merges
// and writes the final softmax outputs for its b (8 KB via L2).
// ---------------------------------------------------------------------------
__global__ void __launch_bounds__(256) k_scores(const float* __restrict__ enc,
                                                float* __restrict__ out) {
    __shared__ float sm_m[8], sm_s[8];
    __shared__ float sm_M, sm_inv;
    __shared__ int s_old;
    const int warp  = threadIdx.x >> 5;
    const int lane  = threadIdx.x & 31;
    const int b     = blockIdx.x >> 4;       // 0..31
    const int chunk = blockIdx.x & 15;       // 0..15
    const int tbase = chunk * 128 + warp * 16;

    // v[b] into registers: 8 float4 per lane (lane covers h = i*128 + lane*4)
    float4 vreg[8];
#pragma unroll
    for (int i = 0; i < 8; i++) {
        vreg[i] = *reinterpret_cast<const float4*>(&g_v[b][i * 128 + lane * 4]);
    }

    float acc[16];
#pragma unroll
    for (int tt = 0; tt < 16; tt++) {
        const int t = tbase + tt;
        const float4* e = reinterpret_cast<const float4*>(
            enc + ((size_t)t * B + b) * H) + lane;   // lane*4 floats in
        float4 a = make_float4(0.f, 0.f, 0.f, 0.f);
#pragma unroll
        for (int i = 0; i < 8; i++) {
            float4 ev = __ldcs(&e[i * 32]);          // h = i*128 + lane*4
            a.x += ev.x * vreg[i].x;
            a.y += ev.y * vreg[i].y;
            a.z += ev.z * vreg[i].z;
            a.w += ev.w * vreg[i].w;
        }
        acc[tt] = (a.x + a.y) + (a.z + a.w);
    }

    // Pipelined multi-value butterfly: 16 independent 5-stage chains.
#pragma unroll
    for (int off = 16; off > 0; off >>= 1) {
#pragma unroll
        for (int i = 0; i < 16; i++)
            acc[i] += __shfl_xor_sync(0xFFFFFFFFu, acc[i], off);
    }

    // per-warp softmax partial (computed after all loads retired)
    float mg = acc[0];
#pragma unroll
    for (int i = 1; i < 16; i++) mg = fmaxf(mg, acc[i]);
    float sg = 0.f;
#pragma unroll
    for (int i = 0; i < 16; i++) sg += __expf(acc[i] - mg);

    if (lane == 0) {
#pragma unroll
        for (int i = 0; i < 16; i++) g_scores[b][tbase + i] = acc[i];
        sm_m[warp] = mg;
        sm_s[warp] = sg;
    }
    __syncthreads();

    // merge 8 warp partials -> chunk partial; publish; take ticket
    if (threadIdx.x == 0) {
        float M = sm_m[0], S = sm_s[0];
#pragma unroll
        for (int i = 1; i < 8; i++) {
            float mi = sm_m[i];
            float nm = fmaxf(M, mi);
            S = S * __expf(M - nm) + sm_s[i] * __expf(mi - nm);
            M = nm;
        }
        g_pm[b][chunk] = M;
        g_ps[b][chunk] = S;
        __threadfence();                              // release
        s_old = atomicAdd(&g_cnts[b], 1);
    }
    __syncthreads();

    if (s_old == NCHUNK - 1) {                        // last chunk of this b
        __threadfence();                              // acquire
        if (threadIdx.x < 32) {
            float m = (lane < NCHUNK) ? g_pm[b][lane] : -INFINITY;
            float s = (lane < NCHUNK) ? g_ps[b][lane] : 0.f;
#pragma unroll
            for (int off = 8; off > 0; off >>= 1) {
                float mo = __shfl_xor_sync(0xFFFFFFFFu, m, off);
                float so = __shfl_xor_sync(0xFFFFFFFFu, s, off);
                float nm = fmaxf(m, mo);
                s = s * __expf(m - nm) + so * __expf(mo - nm);
                m = nm;
            }
            if (lane == 0) { sm_M = m; sm_inv = 1.f / s; }
        }
        __syncthreads();
        const float M = sm_M, inv = sm_inv;
#pragma unroll
        for (int j = 0; j < 2; j++) {
            const int t0 = j * 1024 + threadIdx.x * 4;
            float4 sc = *reinterpret_cast<const float4*>(&g_scores[b][t0]);
            float4 o;
            o.x = __expf(sc.x - M) * inv;
            o.y = __expf(sc.y - M) * inv;
            o.z = __expf(sc.z - M) * inv;
            o.w = __expf(sc.w - M) * inv;
            *reinterpret_cast<float4*>(&out[(size_t)b * T + t0]) = o;
        }
        if (threadIdx.x == 0) g_cnts[b] = 0;          // replay-safe reset
    }
}

// ---------------------------------------------------------------------------
// Inputs (metadata order): hidden [1,B,H], encoderOutput [T,B,H], W [H,H], b [H]
// Output: [B,1,T] float32.  Bias is constant in t -> cancels in softmax.
// ---------------------------------------------------------------------------
extern "C" void kernel_launch(void* const* d_in, const int* in_sizes, int n_in,
                              void* d_out, int out_size) {
    const float* hid = (const float*)d_in[0];
    const float* enc = (const float*)d_in[1];
    const float* W   = (const float*)d_in[2];
    (void)in_sizes; (void)n_in; (void)out_size;
    float* out = (float*)d_out;

    k_vpart<<<dim3(2, 4, KSPLIT), 128>>>(hid, W);
    k_vreduce<<<(B * H + 255) / 256, 256>>>();
    k_scores<<<512, 256>>>(enc, out);
}